// round 15
// baseline (speedup 1.0000x reference)
#include <cuda_runtime.h>
#include <cuda_fp16.h>
#include <cstdint>

// Problem constants
#define BATCH 2
#define HFULL 128
#define WFULL 128
#define CCH   64
#define HLO   64
#define WLO   64
#define LQ    4096          // HLO*WLO
#define KC    576           // 3*3*CCH

static const size_t YSZ = (size_t)BATCH * HFULL * WFULL * CCH; // y output floats

// -------- static device scratch --------
__device__ __align__(16) __half g_Fhf[(size_t)BATCH * LQ * 128]; // f as [hi(64)|lo(64)] per pixel
__device__ float g_n2[BATCH * LQ];                               // ||f_l||^2
__device__ float g_G[(size_t)BATCH * LQ * LQ];                   // Gram of f (C=64 dots)
__device__ float g_T[(size_t)BATCH * LQ * LQ];                   // j-diagonal partial sums
__device__ float g_Z[(size_t)BATCH * LQ * KC];
__device__ __align__(16) __half g_Uhi[(size_t)BATCH * LQ * LQ];
__device__ __align__(16) __half g_Ulo[(size_t)BATCH * LQ * LQ];
__device__ __align__(16) __half g_VT[(size_t)BATCH * KC * LQ];   // [n][j] fp16-quantized
__device__ float g_invden[BATCH * LQ];
__device__ float g_mm[BATCH * LQ];
__device__ int   g_idx[BATCH * LQ];
__device__ int   g_cnt[BATCH * 2];

// ---------------- helpers ----------------
__device__ __forceinline__ uint32_t smem_u32(const void* p) {
    uint32_t a;
    asm("{ .reg .u64 t; cvta.to.shared.u64 t, %1; cvt.u32.u64 %0, t; }" : "=r"(a) : "l"(p));
    return a;
}
__device__ __forceinline__ void cp16(uint32_t dst, const void* src) {
    asm volatile("cp.async.cg.shared.global [%0], [%1], 16;" :: "r"(dst), "l"(src));
}
__device__ __forceinline__ void cp_commit() {
    asm volatile("cp.async.commit_group;");
}
template<int N> __device__ __forceinline__ void cp_wait() {
    asm volatile("cp.async.wait_group %0;" :: "n"(N));
}
__device__ __forceinline__ void ldsm4(uint32_t a, uint32_t& r0, uint32_t& r1, uint32_t& r2, uint32_t& r3) {
    asm volatile("ldmatrix.sync.aligned.m8n8.x4.shared.b16 {%0,%1,%2,%3}, [%4];"
                 : "=r"(r0), "=r"(r1), "=r"(r2), "=r"(r3) : "r"(a));
}
__device__ __forceinline__ void ldsm2(uint32_t a, uint32_t& r0, uint32_t& r1) {
    asm volatile("ldmatrix.sync.aligned.m8n8.x2.shared.b16 {%0,%1}, [%2];"
                 : "=r"(r0), "=r"(r1) : "r"(a));
}
__device__ __forceinline__ void mma16816h(float& c0, float& c1, float& c2, float& c3,
                                          uint32_t a0, uint32_t a1, uint32_t a2, uint32_t a3,
                                          uint32_t b0, uint32_t b1) {
    asm volatile("mma.sync.aligned.m16n8k16.row.col.f32.f16.f16.f32 "
                 "{%0,%1,%2,%3}, {%4,%5,%6,%7}, {%8,%9}, {%0,%1,%2,%3};"
                 : "+f"(c0), "+f"(c1), "+f"(c2), "+f"(c3)
                 : "r"(a0), "r"(a1), "r"(a2), "r"(a3), "r"(b0), "r"(b1));
}
__device__ __forceinline__ uint32_t sw32(int row, int chunk) {
    return (uint32_t)(row * 32 + 16 * (chunk ^ ((row >> 2) & 1)));
}

// ===================================================================
// Kernel 1: build split-fp16 f (avgpool) + per-pixel channel norm^2
// ===================================================================
__global__ void __launch_bounds__(256) build_f_kernel(const float* __restrict__ x)
{
    int b = blockIdx.y;
    int l = blockIdx.x * 4 + (threadIdx.x >> 6);
    int c = threadIdx.x & 63;
    int li = l >> 6, lj = l & 63;

    const size_t xb = (size_t)b * HFULL * WFULL * CCH;
    size_t base = xb + (size_t)(2 * li) * (WFULL * CCH) + (size_t)(2 * lj) * CCH + c;
    float pv = 0.25f * (x[base] + x[base + CCH] + x[base + WFULL * CCH] + x[base + WFULL * CCH + CCH]);

    __half hi = __float2half(pv);
    __half lo = __float2half(pv - __half2float(hi));
    size_t rb = ((size_t)b * LQ + l) * 128;
    g_Fhf[rb + c]      = hi;
    g_Fhf[rb + 64 + c] = lo;

    float sq = pv * pv;
#pragma unroll
    for (int off = 16; off >= 1; off >>= 1)
        sq += __shfl_xor_sync(0xffffffffu, sq, off);
    __shared__ float ws[8];
    int warp = threadIdx.x >> 5;
    if ((threadIdx.x & 31) == 0) ws[warp] = sq;
    __syncthreads();
    if ((threadIdx.x & 63) == 0)
        g_n2[b * LQ + l] = ws[warp] + ws[warp + 1];
}

// ===================================================================
// Kernel 2: mask gate + invden (merged; both map over BATCH*LQ)
// ===================================================================
__global__ void mm_invden_kernel(const float* __restrict__ mask)
{
    int idx = blockIdx.x * blockDim.x + threadIdx.x;
    if (idx >= BATCH * LQ) return;
    int b = idx / LQ;
    int l = idx % LQ;
    int li = l >> 6, lj = l & 63;
    const size_t mb = (size_t)b * HFULL * WFULL;

    float sum9 = 0.0f;
    float sn = 0.0f;
    for (int dh = 0; dh < 3; dh++) {
        for (int dw = 0; dw < 3; dw++) {
            int fi = li - 1 + dh, fj = lj - 1 + dw;
            if (fi >= 0 && fi < HLO && fj >= 0 && fj < WLO) {
                size_t base = mb + (size_t)(2 * fi) * WFULL + (2 * fj);
                sum9 += 0.25f * (mask[base] + mask[base + 1] + mask[base + WFULL] + mask[base + WFULL + 1]);
                sn += g_n2[b * LQ + (fi << 6) + fj];
            }
        }
    }
    float mean = sum9 / 9.0f;
    g_mm[idx] = (mean == 1.0f) ? 1.0f : 0.0f;
    g_invden[idx] = 1.0f / fmaxf(sqrtf(sn), 1e-4f);
}

// ===================================================================
// Kernel 2b: deterministic compaction of active columns (pad to 64)
// ===================================================================
__global__ void __launch_bounds__(1024) compact_kernel()
{
    int b = blockIdx.x;
    int t = threadIdx.x;
    __shared__ int sc[1024];

    int base = t * 4;
    int loc[4];
    int cnt = 0;
#pragma unroll
    for (int i = 0; i < 4; i++) {
        loc[i] = (g_mm[b * LQ + base + i] != 0.0f) ? 1 : 0;
        cnt += loc[i];
    }
    sc[t] = cnt;
    __syncthreads();
    for (int off = 1; off < 1024; off <<= 1) {
        int v = (t >= off) ? sc[t - off] : 0;
        __syncthreads();
        sc[t] += v;
        __syncthreads();
    }
    int pos = sc[t] - cnt;
#pragma unroll
    for (int i = 0; i < 4; i++) {
        if (loc[i]) g_idx[b * LQ + (pos++)] = base + i;
    }
    if (t == 1023) {
        int total = sc[1023];
        int pad = (total + 63) & ~63;
        g_cnt[b * 2 + 0] = total;
        g_cnt[b * 2 + 1] = pad;
        for (int j = total; j < pad; j++) g_idx[b * LQ + j] = 0;
    }
}

// ===================================================================
// Kernel 2c: compacted-transposed fp16 V read straight from x
// ===================================================================
__global__ void __launch_bounds__(256) vcompT_kernel(const float* __restrict__ x)
{
    int b = blockIdx.y;
    int n = blockIdx.x;
    int g = n >> 6;
    int c = n & 63;
    int dh = g / 3, dw = g % 3;
    int cnt = g_cnt[b * 2 + 0];
    int pad = g_cnt[b * 2 + 1];
    const int* __restrict__ idxb = g_idx + b * LQ;
    const float* __restrict__ xb = x + (size_t)b * HFULL * WFULL * CCH;
    __half* __restrict__ Vn = g_VT + ((size_t)b * KC + n) * LQ;

    for (int j = threadIdx.x; j < pad; j += 256) {
        float v = 0.0f;
        if (j < cnt) {
            int l = __ldg(idxb + j);
            int xr = 2 * (l >> 6) + dh;
            int xc = 2 * (l & 63) + dw;
            if (xr < HFULL && xc < WFULL)
                v = __ldg(xb + (size_t)xr * (WFULL * CCH) + (size_t)xc * CCH + c);
        }
        Vn[j] = __float2half(v);
    }
}

// ===================================================================
// Kernel 3a: Gram GEMM G[u][v] = f_u . f_v (K=64) via fp16 3-combo
// float4 epilogue stores.
// ===================================================================
#define STILE 4096
#define SBUF  (4 * STILE)

__global__ void __launch_bounds__(512) gemm_g_kernel()
{
    if (blockIdx.x < blockIdx.y) return;

    __shared__ __align__(16) unsigned char smem_raw[3 * SBUF];  // 48KB

    int t = threadIdx.x;
    int lane = t & 31;
    int wid = t >> 5;
    int warp_m = wid >> 2;
    int warp_n = wid & 3;
    int b = blockIdx.z;
    int p0 = blockIdx.y * 128;
    int q0 = blockIdx.x * 128;

    uint32_t sbase = smem_u32(smem_raw);
    const char* Abase = (const char*)g_Fhf + ((size_t)b * LQ + p0) * 256;
    const char* Bbase = (const char*)g_Fhf + ((size_t)b * LQ + q0) * 256;

    float acc[2][4][4];
#pragma unroll
    for (int i = 0; i < 2; i++)
#pragma unroll
        for (int j = 0; j < 4; j++)
#pragma unroll
            for (int k = 0; k < 4; k++) acc[i][j][k] = 0.0f;

    const int NIT = 4;
    auto stage = [&](int buf, int kc) {
        uint32_t sdst = sbase + buf * SBUF;
        size_t col = (size_t)kc * 32;
#pragma unroll
        for (int r = 0; r < 2; r++) {
            int id = r * 512 + t;
            int tile = id >> 8;
            int rid = id & 255;
            int row = rid >> 1, u = rid & 1;
            const char* src = (tile < 2 ? Abase : Bbase)
                            + (size_t)row * 256 + col
                            + ((tile & 1) ? 128 : 0)
                            + u * 16;
            cp16(sdst + tile * STILE + sw32(row, u), src);
        }
    };

    int lr = lane & 7, sel = lane >> 3;
    auto compute = [&](int buf) {
        uint32_t sAhi = sbase + buf * SBUF;
        uint32_t sAlo = sAhi + STILE;
        uint32_t sBhi = sAhi + 2 * STILE;
        uint32_t sBlo = sAhi + 3 * STILE;

        uint32_t ah[2][4], al[2][4];
#pragma unroll
        for (int mt = 0; mt < 2; mt++) {
            int row = warp_m * 32 + mt * 16 + lr + (sel & 1) * 8;
            int cc = sel >> 1;
            ldsm4(sAhi + sw32(row, cc), ah[mt][0], ah[mt][1], ah[mt][2], ah[mt][3]);
            ldsm4(sAlo + sw32(row, cc), al[mt][0], al[mt][1], al[mt][2], al[mt][3]);
        }
        uint32_t bh[2][4], bl[2][4];
#pragma unroll
        for (int ntp = 0; ntp < 2; ntp++) {
            int row = warp_n * 32 + ntp * 16 + lr + (sel >> 1) * 8;
            int cc = sel & 1;
            ldsm4(sBhi + sw32(row, cc), bh[ntp][0], bh[ntp][1], bh[ntp][2], bh[ntp][3]);
            ldsm4(sBlo + sw32(row, cc), bl[ntp][0], bl[ntp][1], bl[ntp][2], bl[ntp][3]);
        }
#pragma unroll
        for (int mt = 0; mt < 2; mt++)
#pragma unroll
            for (int nt = 0; nt < 4; nt++) {
                int g = nt >> 1, h = (nt & 1) * 2;
                mma16816h(acc[mt][nt][0], acc[mt][nt][1], acc[mt][nt][2], acc[mt][nt][3],
                          ah[mt][0], ah[mt][1], ah[mt][2], ah[mt][3], bh[g][h], bh[g][h + 1]);
                mma16816h(acc[mt][nt][0], acc[mt][nt][1], acc[mt][nt][2], acc[mt][nt][3],
                          ah[mt][0], ah[mt][1], ah[mt][2], ah[mt][3], bl[g][h], bl[g][h + 1]);
                mma16816h(acc[mt][nt][0], acc[mt][nt][1], acc[mt][nt][2], acc[mt][nt][3],
                          al[mt][0], al[mt][1], al[mt][2], al[mt][3], bh[g][h], bh[g][h + 1]);
            }
    };

    stage(0, 0);
    cp_commit();
    for (int it = 0; it < NIT; it++) {
        if (it + 1 < NIT) {
            stage((it + 1) % 3, it + 1);
            cp_commit();
            cp_wait<1>();
        } else {
            cp_wait<0>();
        }
        __syncthreads();
        compute(it % 3);
    }

    float* __restrict__ Gb = g_G + (size_t)b * LQ * LQ;
    float* S = (float*)smem_raw;

#pragma unroll
    for (int mhalf = 0; mhalf < 2; mhalf++) {
        __syncthreads();
        if ((warp_m >> 1) == mhalf) {
            int r0l = lane >> 2;
            int c0l = (lane & 3) * 2;
#pragma unroll
            for (int mt = 0; mt < 2; mt++)
#pragma unroll
                for (int nt = 0; nt < 4; nt++) {
                    int rr = (warp_m & 1) * 32 + mt * 16 + r0l;
                    int cc = warp_n * 32 + nt * 8 + c0l;
                    S[rr * 132 + cc]           = acc[mt][nt][0];
                    S[rr * 132 + cc + 1]       = acc[mt][nt][1];
                    S[(rr + 8) * 132 + cc]     = acc[mt][nt][2];
                    S[(rr + 8) * 132 + cc + 1] = acc[mt][nt][3];
                }
        }
        __syncthreads();
        // normal half: float4 stores
        {
            int r = t >> 3, cs = (t & 7) * 16;
            float4* dst = (float4*)(Gb + (size_t)(p0 + mhalf * 64 + r) * LQ + q0 + cs);
            const float* sp = S + r * 132 + cs;
#pragma unroll
            for (int j = 0; j < 4; j++)
                dst[j] = *(const float4*)(sp + j * 4);
        }
        // mirrored half: float4 stores along p
        {
            int c = t >> 2, rs = (t & 3) * 16;
            float* dst = Gb + (size_t)(q0 + c) * LQ + p0 + mhalf * 64 + rs;
#pragma unroll
            for (int j = 0; j < 4; j++) {
                float4 w = make_float4(S[(rs + 4 * j) * 132 + c],
                                       S[(rs + 4 * j + 1) * 132 + c],
                                       S[(rs + 4 * j + 2) * 132 + c],
                                       S[(rs + 4 * j + 3) * 132 + c]);
                *(float4*)(dst + 4 * j) = w;
            }
        }
    }
}

// ===================================================================
// Kernel 3b: pass1 (j-diagonal), float4, 4 consecutive u per block
// (rows u0-1..u0+4 stay L1-hot across the 4 sub-rows).
// T[u][v] = G[u][v] + G[u-1][v-1](uj>0,vj>0) + G[u+1][v+1](uj<63,vj<63)
// ===================================================================
__global__ void __launch_bounds__(256) diag1_kernel()
{
    int b = blockIdx.y;
    int u0 = blockIdx.x * 4;
    const float* __restrict__ Gb = g_G + (size_t)b * LQ * LQ;

    for (int su = 0; su < 4; su++) {
        int u = u0 + su;
        int uj = u & 63;
        const float4* __restrict__ r04 = (const float4*)(Gb + (size_t)u * LQ);
        const float4* __restrict__ rm4 = (const float4*)(Gb + (size_t)(u - 1) * LQ);
        const float4* __restrict__ rp4 = (const float4*)(Gb + (size_t)(u + 1) * LQ);
        const float* __restrict__ rmf = Gb + (size_t)(u - 1) * LQ;
        const float* __restrict__ rpf = Gb + (size_t)(u + 1) * LQ;
        float4* __restrict__ Tu = (float4*)(g_T + (size_t)b * LQ * LQ + (size_t)u * LQ);
        bool um = (uj > 0), up = (uj < 63);

        for (int i = threadIdx.x; i < 1024; i += 256) {
            int v = i * 4;
            float4 o = __ldg(r04 + i);
            if (um) {
                float4 m = __ldg(rm4 + i);
                if (v & 63) o.x += __ldg(rmf + v - 1);
                o.y += m.x; o.z += m.y; o.w += m.z;
            }
            if (up) {
                float4 pq = __ldg(rp4 + i);
                o.x += pq.y; o.y += pq.z; o.z += pq.w;
                if ((v & 63) != 60) o.w += __ldg(rpf + v + 4);
            }
            Tu[i] = o;
        }
    }
}

// ===================================================================
// Kernel 3c: pass2 (i-diagonal) + inv scale, float4, 4 pi-consecutive
// p (same pj) per block: T rows (pi0-1..pi0+4)*64+pj stay L1-hot.
// att[p][q] = (T[p][q] + T[p-64][q-64](pi>0,qi>0)
//              + T[p+64][q+64](pi<63,qi<63)) * inv[q]
// ===================================================================
__global__ void __launch_bounds__(256) diag2_kernel(float* __restrict__ out)
{
    int b = blockIdx.y;
    int bx = blockIdx.x;           // 0..1023
    int pj = bx & 63;
    int pi0 = (bx >> 6) * 4;
    const float* __restrict__ Tb = g_T + (size_t)b * LQ * LQ;
    const float4* __restrict__ inv4 = (const float4*)(g_invden + b * LQ);

    for (int sp = 0; sp < 4; sp++) {
        int pi = pi0 + sp;
        int p = (pi << 6) | pj;
        const float4* __restrict__ r04 = (const float4*)(Tb + (size_t)p * LQ);
        const float4* __restrict__ rm4 = (const float4*)(Tb + (size_t)(p - 64) * LQ);
        const float4* __restrict__ rp4 = (const float4*)(Tb + (size_t)(p + 64) * LQ);
        float4* __restrict__ orow = (float4*)(out + YSZ + (size_t)b * LQ * LQ + (size_t)p * LQ);
        bool um = (pi > 0), up = (pi < 63);

        for (int i = threadIdx.x; i < 1024; i += 256) {
            int qi = i >> 4;
            float4 o = __ldg(r04 + i);
            if (um && qi > 0) {
                float4 m = __ldg(rm4 + i - 16);
                o.x += m.x; o.y += m.y; o.z += m.z; o.w += m.w;
            }
            if (up && qi < 63) {
                float4 pq = __ldg(rp4 + i + 16);
                o.x += pq.x; o.y += pq.y; o.z += pq.z; o.w += pq.w;
            }
            float4 iv = __ldg(inv4 + i);
            o.x *= iv.x; o.y *= iv.y; o.z *= iv.z; o.w *= iv.w;
            orow[i] = o;
        }
    }
}

// ===================================================================
// Kernel 4: fuse + stable softmax -> split-fp16 U (8 p per block)
// ===================================================================
__global__ void __launch_bounds__(256) fuse_softmax_kernel(const float* __restrict__ out)
{
    int b = blockIdx.y;
    int bx = blockIdx.x;
    int qj = bx & 63;
    int qi0 = (bx >> 6) << 3;

    const float* __restrict__ ab = out + YSZ + (size_t)b * LQ * LQ;
    const int* __restrict__ idxb = g_idx + b * LQ;

    int cnt = g_cnt[b * 2 + 0];
    int pad = g_cnt[b * 2 + 1];

    __shared__ float zbuf[LQ];
    __shared__ float red[256];

    int t = threadIdx.x;

    for (int sub = 0; sub < 8; sub++) {
        int qi = qi0 + sub;
        int p = (qi << 6) | qj;
        int ap = (qj << 6) | qi;
        __half* __restrict__ Uhp = g_Uhi + ((size_t)b * LQ + p) * LQ;
        __half* __restrict__ Ulp = g_Ulo + ((size_t)b * LQ + p) * LQ;

        float lmax = (cnt < LQ) ? 0.0f : -3.4e38f;

        for (int j = t; j < pad; j += 256) {
            float z = 0.0f;
            if (j < cnt) {
                int l = __ldg(idxb + j);
                int ki = l >> 6, kj = l & 63;
                int bp = (kj << 6) | ki;
                float acc = 0.0f;
#pragma unroll
                for (int d2 = -1; d2 <= 1; d2++) {
                    int aa = ap + d2;
                    int bb = bp + d2;
                    if ((unsigned)aa < LQ && (unsigned)bb < LQ) {
                        int u0 = ((aa & 63) << 6) | (aa >> 6);
                        int v0 = ((bb & 63) << 6) | (bb >> 6);
#pragma unroll
                        for (int d1 = -1; d1 <= 1; d1++) {
                            int uu = u0 + d1, vv = v0 + d1;
                            if ((unsigned)uu < LQ && (unsigned)vv < LQ)
                                acc += __ldg(ab + (size_t)uu * LQ + vv);
                        }
                    }
                }
                z = acc * 10.0f;
                lmax = fmaxf(lmax, z);
            }
            zbuf[j] = z;
        }

        red[t] = lmax;
        __syncthreads();
        for (int off = 128; off >= 1; off >>= 1) {
            if (t < off) red[t] = fmaxf(red[t], red[t + off]);
            __syncthreads();
        }
        float rmax = red[0];
        __syncthreads();

        float lsum = 0.0f;
        for (int j = t; j < pad; j += 256) {
            float e = 0.0f;
            if (j < cnt) {
                e = expf(zbuf[j] - rmax);
                lsum += e;
            }
            zbuf[j] = e;
        }
        red[t] = lsum;
        __syncthreads();
        for (int off = 128; off >= 1; off >>= 1) {
            if (t < off) red[t] += red[t + off];
            __syncthreads();
        }
        float den = red[0] + (float)(LQ - cnt) * expf(-rmax);
        float invs = 1.0f / den;
        __syncthreads();

        for (int j = t; j < pad; j += 256) {
            float val = zbuf[j] * invs;
            __half hi = __float2half(val);
            Uhp[j] = hi;
            Ulp[j] = __float2half(val - __half2float(hi));
        }
        __syncthreads();
    }
}

// ===================================================================
// Kernel 5: recon GEMM via fp16 mma.sync, 2-combo:
// Z = (Uhi + Ulo) @ fp16(V)^T. 128x96 tile, warp 64x24, BK=16,
// 4-stage ring, 2 CTAs/SM.
// ===================================================================
#define ZTA 4096
#define ZTB 3072
#define ZBUF (2 * ZTA + ZTB)

__global__ void __launch_bounds__(256, 2) gemm_z_mma_kernel()
{
    __shared__ __align__(16) unsigned char smem_raw[4 * ZBUF];  // 44KB

    int t = threadIdx.x;
    int lane = t & 31;
    int wid = t >> 5;
    int warp_m = wid >> 2;
    int warp_n = wid & 3;
    int b = blockIdx.z;
    int p0 = blockIdx.y * 128;
    int n0 = blockIdx.x * 96;

    int kmax = g_cnt[b * 2 + 1];
    int NIT = kmax >> 4;

    uint32_t sbase = smem_u32(smem_raw);
    const char* Ah = (const char*)(g_Uhi + ((size_t)b * LQ + p0) * LQ);
    const char* Al = (const char*)(g_Ulo + ((size_t)b * LQ + p0) * LQ);
    const char* Bh = (const char*)(g_VT + ((size_t)b * KC + n0) * LQ);

    float acc[4][3][4];
#pragma unroll
    for (int i = 0; i < 4; i++)
#pragma unroll
        for (int j = 0; j < 3; j++)
#pragma unroll
            for (int k = 0; k < 4; k++) acc[i][j][k] = 0.0f;

    auto stage = [&](int buf, int kc) {
        uint32_t sdst = sbase + buf * ZBUF;
        size_t col = (size_t)kc * 32;
        for (int i = t; i < 704; i += 256) {
            if (i < 512) {
                const char* src = (i < 256) ? Ah : Al;
                uint32_t base = sdst + ((i < 256) ? 0 : ZTA);
                int rid = i & 255;
                int row = rid >> 1, u = rid & 1;
                cp16(base + sw32(row, u), src + (size_t)row * (LQ * 2) + col + u * 16);
            } else {
                int j = i - 512;
                int row = j >> 1, u = j & 1;
                cp16(sdst + 2 * ZTA + sw32(row, u), Bh + (size_t)row * (LQ * 2) + col + u * 16);
            }
        }
    };

    int lr = lane & 7, sel = lane >> 3;
    int half2 = (lane >> 3) & 1;
    auto compute = [&](int buf) {
        uint32_t sAh = sbase + buf * ZBUF;
        uint32_t sAl = sAh + ZTA;
        uint32_t sBh = sAh + 2 * ZTA;

        uint32_t ah[4][4], al[4][4];
#pragma unroll
        for (int mt = 0; mt < 4; mt++) {
            int row = warp_m * 64 + mt * 16 + lr + (sel & 1) * 8;
            int cc = sel >> 1;
            ldsm4(sAh + sw32(row, cc), ah[mt][0], ah[mt][1], ah[mt][2], ah[mt][3]);
            ldsm4(sAl + sw32(row, cc), al[mt][0], al[mt][1], al[mt][2], al[mt][3]);
        }
        uint32_t bh[6];
        {
            int row = warp_n * 24 + lr + (sel >> 1) * 8;
            int cc = sel & 1;
            ldsm4(sBh + sw32(row, cc), bh[0], bh[1], bh[2], bh[3]);
        }
        {
            int row = warp_n * 24 + 16 + lr;
            int cc = half2;
            ldsm2(sBh + sw32(row, cc), bh[4], bh[5]);
        }
#pragma unroll
        for (int mt = 0; mt < 4; mt++)
#pragma unroll
            for (int nt = 0; nt < 3; nt++) {
                mma16816h(acc[mt][nt][0], acc[mt][nt][1], acc[mt][nt][2], acc[mt][nt][3],
                          ah[mt][0], ah[mt][1], ah[mt][2], ah[mt][3], bh[nt * 2], bh[nt * 2 + 1]);
                mma16816h(acc[mt][nt][0], acc[mt][nt][1], acc[mt][nt][2], acc[mt][nt][3],
                          al[mt][0], al[mt][1], al[mt][2], al[mt][3], bh[nt * 2], bh[nt * 2 + 1]);
            }
    };

    stage(0, 0); cp_commit();
    stage(1, 1); cp_commit();
    for (int it = 0; it < NIT; it++) {
        if (it + 2 < NIT) {
            stage((it + 2) & 3, it + 2);
            cp_commit();
            cp_wait<2>();
        } else if (it + 1 < NIT) {
            cp_wait<1>();
        } else {
            cp_wait<0>();
        }
        __syncthreads();
        compute(it & 3);
    }

    float* __restrict__ Zb = g_Z + (size_t)b * LQ * KC;
    int r0l = lane >> 2;
    int c0l = (lane & 3) * 2;
#pragma unroll
    for (int mt = 0; mt < 4; mt++)
#pragma unroll
        for (int nt = 0; nt < 3; nt++) {
            int row = p0 + warp_m * 64 + mt * 16 + r0l;
            int col = n0 + warp_n * 24 + nt * 8 + c0l;
            *(float2*)(Zb + (size_t)row * KC + col) =
                make_float2(acc[mt][nt][0], acc[mt][nt][1]);
            *(float2*)(Zb + (size_t)(row + 8) * KC + col) =
                make_float2(acc[mt][nt][2], acc[mt][nt][3]);
        }
}

// ===================================================================
// Kernel 6: overlap-add (transposed conv gather), float4 per thread
// ===================================================================
__global__ void recon_kernel(float* __restrict__ out)
{
    int idx = blockIdx.x * blockDim.x + threadIdx.x;
    if (idx >= (int)(YSZ / 4)) return;
    int c4 = (idx & 15) * 4;
    int tmp = idx >> 4;
    int J = tmp & 127; tmp >>= 7;
    int I = tmp & 127;
    int b = tmp >> 7;

    int ri[2], rdh[2], rn = 0;
    if (I & 1) { ri[0] = (I - 1) >> 1; rdh[0] = 1; rn = 1; }
    else {
        ri[rn] = I >> 1; rdh[rn] = 0; rn++;
        if (I >= 2) { ri[rn] = (I >> 1) - 1; rdh[rn] = 2; rn++; }
    }
    int cj[2], cdw[2], cn = 0;
    if (J & 1) { cj[0] = (J - 1) >> 1; cdw[0] = 1; cn = 1; }
    else {
        cj[cn] = J >> 1; cdw[cn] = 0; cn++;
        if (J >= 2) { cj[cn] = (J >> 1) - 1; cdw[cn] = 2; cn++; }
    }

    const float* __restrict__ Zb = g_Z + (size_t)b * LQ * KC;
    float4 acc = make_float4(0.f, 0.f, 0.f, 0.f);
    for (int a = 0; a < rn; a++) {
        for (int bb = 0; bb < cn; bb++) {
            int l = ri[a] * 64 + cj[bb];
            int n = (rdh[a] * 3 + cdw[bb]) * 64 + c4;
            float4 v = *(const float4*)(Zb + (size_t)l * KC + n);
            acc.x += v.x; acc.y += v.y; acc.z += v.z; acc.w += v.w;
        }
    }
    acc.x *= 0.25f; acc.y *= 0.25f; acc.z *= 0.25f; acc.w *= 0.25f;
    size_t o = (((size_t)b * HFULL + I) * WFULL + J) * CCH + c4;
    *(float4*)(out + o) = acc;
}

// ===================================================================
extern "C" void kernel_launch(void* const* d_in, const int* in_sizes, int n_in,
                              void* d_out, int out_size)
{
    const float* x    = (const float*)d_in[0];
    const float* mask = (const float*)d_in[1];
    float* out = (float*)d_out;
    (void)in_sizes; (void)n_in; (void)out_size;

    build_f_kernel<<<dim3(LQ / 4, BATCH), 256>>>(x);
    mm_invden_kernel<<<(BATCH * LQ + 255) / 256, 256>>>(mask);
    compact_kernel<<<BATCH, 1024>>>();
    vcompT_kernel<<<dim3(KC, BATCH), 256>>>(x);
    gemm_g_kernel<<<dim3(32, 32, BATCH), 512>>>();
    diag1_kernel<<<dim3(LQ / 4, BATCH), 256>>>();
    diag2_kernel<<<dim3(1024, BATCH), 256>>>(out);
    fuse_softmax_kernel<<<dim3(512, BATCH), 256>>>(out);
    gemm_z_mma_kernel<<<dim3(6, 32, BATCH), 256>>>();
    recon_kernel<<<(int)(YSZ / 4 + 255) / 256, 256>>>(out);
}

// round 16
// speedup vs baseline: 1.0885x; 1.0885x over previous
#include <cuda_runtime.h>
#include <cuda_fp16.h>
#include <cstdint>

// Problem constants
#define BATCH 2
#define HFULL 128
#define WFULL 128
#define CCH   64
#define HLO   64
#define WLO   64
#define LQ    4096          // HLO*WLO
#define KC    576           // 3*3*CCH

static const size_t YSZ = (size_t)BATCH * HFULL * WFULL * CCH; // y output floats

// -------- static device scratch --------
__device__ __align__(16) __half g_Fhf[(size_t)BATCH * LQ * 128]; // f as [hi(64)|lo(64)] per pixel
__device__ float g_n2[BATCH * LQ];                               // ||f_l||^2
__device__ float g_G[(size_t)BATCH * LQ * LQ];                   // Gram of f (C=64 dots)
__device__ float g_T[(size_t)BATCH * LQ * LQ];                   // j-diagonal partial sums
__device__ float g_Z[(size_t)BATCH * LQ * KC];
__device__ __align__(16) __half g_Uhi[(size_t)BATCH * LQ * LQ];
__device__ __align__(16) __half g_Ulo[(size_t)BATCH * LQ * LQ];
__device__ __align__(16) __half g_VT[(size_t)BATCH * KC * LQ];   // [n][j] fp16-quantized
__device__ float g_invden[BATCH * LQ];
__device__ float g_mm[BATCH * LQ];
__device__ int   g_idx[BATCH * LQ];
__device__ int   g_cnt[BATCH * 2];

// ---------------- helpers ----------------
__device__ __forceinline__ uint32_t smem_u32(const void* p) {
    uint32_t a;
    asm("{ .reg .u64 t; cvta.to.shared.u64 t, %1; cvt.u32.u64 %0, t; }" : "=r"(a) : "l"(p));
    return a;
}
__device__ __forceinline__ void cp16(uint32_t dst, const void* src) {
    asm volatile("cp.async.cg.shared.global [%0], [%1], 16;" :: "r"(dst), "l"(src));
}
__device__ __forceinline__ void cp_commit() {
    asm volatile("cp.async.commit_group;");
}
template<int N> __device__ __forceinline__ void cp_wait() {
    asm volatile("cp.async.wait_group %0;" :: "n"(N));
}
__device__ __forceinline__ void ldsm4(uint32_t a, uint32_t& r0, uint32_t& r1, uint32_t& r2, uint32_t& r3) {
    asm volatile("ldmatrix.sync.aligned.m8n8.x4.shared.b16 {%0,%1,%2,%3}, [%4];"
                 : "=r"(r0), "=r"(r1), "=r"(r2), "=r"(r3) : "r"(a));
}
__device__ __forceinline__ void ldsm2(uint32_t a, uint32_t& r0, uint32_t& r1) {
    asm volatile("ldmatrix.sync.aligned.m8n8.x2.shared.b16 {%0,%1}, [%2];"
                 : "=r"(r0), "=r"(r1) : "r"(a));
}
__device__ __forceinline__ void mma16816h(float& c0, float& c1, float& c2, float& c3,
                                          uint32_t a0, uint32_t a1, uint32_t a2, uint32_t a3,
                                          uint32_t b0, uint32_t b1) {
    asm volatile("mma.sync.aligned.m16n8k16.row.col.f32.f16.f16.f32 "
                 "{%0,%1,%2,%3}, {%4,%5,%6,%7}, {%8,%9}, {%0,%1,%2,%3};"
                 : "+f"(c0), "+f"(c1), "+f"(c2), "+f"(c3)
                 : "r"(a0), "r"(a1), "r"(a2), "r"(a3), "r"(b0), "r"(b1));
}
__device__ __forceinline__ uint32_t sw32(int row, int chunk) {
    return (uint32_t)(row * 32 + 16 * (chunk ^ ((row >> 2) & 1)));
}

// ===================================================================
// Kernel 1: build split-fp16 f (avgpool) + per-pixel channel norm^2
// ===================================================================
__global__ void __launch_bounds__(256) build_f_kernel(const float* __restrict__ x)
{
    int b = blockIdx.y;
    int l = blockIdx.x * 4 + (threadIdx.x >> 6);
    int c = threadIdx.x & 63;
    int li = l >> 6, lj = l & 63;

    const size_t xb = (size_t)b * HFULL * WFULL * CCH;
    size_t base = xb + (size_t)(2 * li) * (WFULL * CCH) + (size_t)(2 * lj) * CCH + c;
    float pv = 0.25f * (x[base] + x[base + CCH] + x[base + WFULL * CCH] + x[base + WFULL * CCH + CCH]);

    __half hi = __float2half(pv);
    __half lo = __float2half(pv - __half2float(hi));
    size_t rb = ((size_t)b * LQ + l) * 128;
    g_Fhf[rb + c]      = hi;
    g_Fhf[rb + 64 + c] = lo;

    float sq = pv * pv;
#pragma unroll
    for (int off = 16; off >= 1; off >>= 1)
        sq += __shfl_xor_sync(0xffffffffu, sq, off);
    __shared__ float ws[8];
    int warp = threadIdx.x >> 5;
    if ((threadIdx.x & 31) == 0) ws[warp] = sq;
    __syncthreads();
    if ((threadIdx.x & 63) == 0)
        g_n2[b * LQ + l] = ws[warp] + ws[warp + 1];
}

// ===================================================================
// Kernel 2: mask gate + invden merged (same 3x3 validity loop)
// ===================================================================
__global__ void mm_invden_kernel(const float* __restrict__ mask)
{
    int idx = blockIdx.x * blockDim.x + threadIdx.x;
    if (idx >= BATCH * LQ) return;
    int b = idx / LQ;
    int l = idx % LQ;
    int li = l >> 6, lj = l & 63;
    const size_t mb = (size_t)b * HFULL * WFULL;

    float sum9 = 0.0f;
    float sn = 0.0f;
    for (int dh = 0; dh < 3; dh++) {
        for (int dw = 0; dw < 3; dw++) {
            int fi = li - 1 + dh, fj = lj - 1 + dw;
            if (fi >= 0 && fi < HLO && fj >= 0 && fj < WLO) {
                size_t base = mb + (size_t)(2 * fi) * WFULL + (2 * fj);
                sum9 += 0.25f * (mask[base] + mask[base + 1] + mask[base + WFULL] + mask[base + WFULL + 1]);
                sn += g_n2[b * LQ + (fi << 6) + fj];
            }
        }
    }
    float mean = sum9 / 9.0f;
    g_mm[idx] = (mean == 1.0f) ? 1.0f : 0.0f;
    g_invden[idx] = 1.0f / fmaxf(sqrtf(sn), 1e-4f);
}

// ===================================================================
// Kernel 2b: deterministic compaction of active columns (pad to 64)
// ===================================================================
__global__ void __launch_bounds__(1024) compact_kernel()
{
    int b = blockIdx.x;
    int t = threadIdx.x;
    __shared__ int sc[1024];

    int base = t * 4;
    int loc[4];
    int cnt = 0;
#pragma unroll
    for (int i = 0; i < 4; i++) {
        loc[i] = (g_mm[b * LQ + base + i] != 0.0f) ? 1 : 0;
        cnt += loc[i];
    }
    sc[t] = cnt;
    __syncthreads();
    for (int off = 1; off < 1024; off <<= 1) {
        int v = (t >= off) ? sc[t - off] : 0;
        __syncthreads();
        sc[t] += v;
        __syncthreads();
    }
    int pos = sc[t] - cnt;
#pragma unroll
    for (int i = 0; i < 4; i++) {
        if (loc[i]) g_idx[b * LQ + (pos++)] = base + i;
    }
    if (t == 1023) {
        int total = sc[1023];
        int pad = (total + 63) & ~63;
        g_cnt[b * 2 + 0] = total;
        g_cnt[b * 2 + 1] = pad;
        for (int j = total; j < pad; j++) g_idx[b * LQ + j] = 0;
    }
}

// ===================================================================
// Kernel 2c: compacted-transposed fp16 V read straight from x
// ===================================================================
__global__ void __launch_bounds__(256) vcompT_kernel(const float* __restrict__ x)
{
    int b = blockIdx.y;
    int n = blockIdx.x;
    int g = n >> 6;
    int c = n & 63;
    int dh = g / 3, dw = g % 3;
    int cnt = g_cnt[b * 2 + 0];
    int pad = g_cnt[b * 2 + 1];
    const int* __restrict__ idxb = g_idx + b * LQ;
    const float* __restrict__ xb = x + (size_t)b * HFULL * WFULL * CCH;
    __half* __restrict__ Vn = g_VT + ((size_t)b * KC + n) * LQ;

    for (int j = threadIdx.x; j < pad; j += 256) {
        float v = 0.0f;
        if (j < cnt) {
            int l = __ldg(idxb + j);
            int xr = 2 * (l >> 6) + dh;
            int xc = 2 * (l & 63) + dw;
            if (xr < HFULL && xc < WFULL)
                v = __ldg(xb + (size_t)xr * (WFULL * CCH) + (size_t)xc * CCH + c);
        }
        Vn[j] = __float2half(v);
    }
}

// ===================================================================
// Kernel 3a: Gram GEMM G[u][v] = f_u . f_v (K=64) via fp16 3-combo
// float4 epilogue stores.
// ===================================================================
#define STILE 4096
#define SBUF  (4 * STILE)

__global__ void __launch_bounds__(512) gemm_g_kernel()
{
    if (blockIdx.x < blockIdx.y) return;

    __shared__ __align__(16) unsigned char smem_raw[3 * SBUF];  // 48KB

    int t = threadIdx.x;
    int lane = t & 31;
    int wid = t >> 5;
    int warp_m = wid >> 2;
    int warp_n = wid & 3;
    int b = blockIdx.z;
    int p0 = blockIdx.y * 128;
    int q0 = blockIdx.x * 128;

    uint32_t sbase = smem_u32(smem_raw);
    const char* Abase = (const char*)g_Fhf + ((size_t)b * LQ + p0) * 256;
    const char* Bbase = (const char*)g_Fhf + ((size_t)b * LQ + q0) * 256;

    float acc[2][4][4];
#pragma unroll
    for (int i = 0; i < 2; i++)
#pragma unroll
        for (int j = 0; j < 4; j++)
#pragma unroll
            for (int k = 0; k < 4; k++) acc[i][j][k] = 0.0f;

    const int NIT = 4;
    auto stage = [&](int buf, int kc) {
        uint32_t sdst = sbase + buf * SBUF;
        size_t col = (size_t)kc * 32;
#pragma unroll
        for (int r = 0; r < 2; r++) {
            int id = r * 512 + t;
            int tile = id >> 8;
            int rid = id & 255;
            int row = rid >> 1, u = rid & 1;
            const char* src = (tile < 2 ? Abase : Bbase)
                            + (size_t)row * 256 + col
                            + ((tile & 1) ? 128 : 0)
                            + u * 16;
            cp16(sdst + tile * STILE + sw32(row, u), src);
        }
    };

    int lr = lane & 7, sel = lane >> 3;
    auto compute = [&](int buf) {
        uint32_t sAhi = sbase + buf * SBUF;
        uint32_t sAlo = sAhi + STILE;
        uint32_t sBhi = sAhi + 2 * STILE;
        uint32_t sBlo = sAhi + 3 * STILE;

        uint32_t ah[2][4], al[2][4];
#pragma unroll
        for (int mt = 0; mt < 2; mt++) {
            int row = warp_m * 32 + mt * 16 + lr + (sel & 1) * 8;
            int cc = sel >> 1;
            ldsm4(sAhi + sw32(row, cc), ah[mt][0], ah[mt][1], ah[mt][2], ah[mt][3]);
            ldsm4(sAlo + sw32(row, cc), al[mt][0], al[mt][1], al[mt][2], al[mt][3]);
        }
        uint32_t bh[2][4], bl[2][4];
#pragma unroll
        for (int ntp = 0; ntp < 2; ntp++) {
            int row = warp_n * 32 + ntp * 16 + lr + (sel >> 1) * 8;
            int cc = sel & 1;
            ldsm4(sBhi + sw32(row, cc), bh[ntp][0], bh[ntp][1], bh[ntp][2], bh[ntp][3]);
            ldsm4(sBlo + sw32(row, cc), bl[ntp][0], bl[ntp][1], bl[ntp][2], bl[ntp][3]);
        }
#pragma unroll
        for (int mt = 0; mt < 2; mt++)
#pragma unroll
            for (int nt = 0; nt < 4; nt++) {
                int g = nt >> 1, h = (nt & 1) * 2;
                mma16816h(acc[mt][nt][0], acc[mt][nt][1], acc[mt][nt][2], acc[mt][nt][3],
                          ah[mt][0], ah[mt][1], ah[mt][2], ah[mt][3], bh[g][h], bh[g][h + 1]);
                mma16816h(acc[mt][nt][0], acc[mt][nt][1], acc[mt][nt][2], acc[mt][nt][3],
                          ah[mt][0], ah[mt][1], ah[mt][2], ah[mt][3], bl[g][h], bl[g][h + 1]);
                mma16816h(acc[mt][nt][0], acc[mt][nt][1], acc[mt][nt][2], acc[mt][nt][3],
                          al[mt][0], al[mt][1], al[mt][2], al[mt][3], bh[g][h], bh[g][h + 1]);
            }
    };

    stage(0, 0);
    cp_commit();
    for (int it = 0; it < NIT; it++) {
        if (it + 1 < NIT) {
            stage((it + 1) % 3, it + 1);
            cp_commit();
            cp_wait<1>();
        } else {
            cp_wait<0>();
        }
        __syncthreads();
        compute(it % 3);
    }

    float* __restrict__ Gb = g_G + (size_t)b * LQ * LQ;
    float* S = (float*)smem_raw;

#pragma unroll
    for (int mhalf = 0; mhalf < 2; mhalf++) {
        __syncthreads();
        if ((warp_m >> 1) == mhalf) {
            int r0l = lane >> 2;
            int c0l = (lane & 3) * 2;
#pragma unroll
            for (int mt = 0; mt < 2; mt++)
#pragma unroll
                for (int nt = 0; nt < 4; nt++) {
                    int rr = (warp_m & 1) * 32 + mt * 16 + r0l;
                    int cc = warp_n * 32 + nt * 8 + c0l;
                    S[rr * 132 + cc]           = acc[mt][nt][0];
                    S[rr * 132 + cc + 1]       = acc[mt][nt][1];
                    S[(rr + 8) * 132 + cc]     = acc[mt][nt][2];
                    S[(rr + 8) * 132 + cc + 1] = acc[mt][nt][3];
                }
        }
        __syncthreads();
        // normal half: float4 stores
        {
            int r = t >> 3, cs = (t & 7) * 16;
            float4* dst = (float4*)(Gb + (size_t)(p0 + mhalf * 64 + r) * LQ + q0 + cs);
            const float* sp = S + r * 132 + cs;
#pragma unroll
            for (int j = 0; j < 4; j++)
                dst[j] = *(const float4*)(sp + j * 4);
        }
        // mirrored half: float4 stores along p
        {
            int c = t >> 2, rs = (t & 3) * 16;
            float* dst = Gb + (size_t)(q0 + c) * LQ + p0 + mhalf * 64 + rs;
#pragma unroll
            for (int j = 0; j < 4; j++) {
                float4 w = make_float4(S[(rs + 4 * j) * 132 + c],
                                       S[(rs + 4 * j + 1) * 132 + c],
                                       S[(rs + 4 * j + 2) * 132 + c],
                                       S[(rs + 4 * j + 3) * 132 + c]);
                *(float4*)(dst + 4 * j) = w;
            }
        }
    }
}

// ===================================================================
// Kernel 3b: pass1 (j-diagonal), float4 vectorized (R13 config):
// T[u][v] = G[u][v] + G[u-1][v-1](uj>0,vj>0) + G[u+1][v+1](uj<63,vj<63)
// ===================================================================
__global__ void __launch_bounds__(256) diag1_kernel()
{
    int b = blockIdx.y;
    int u = blockIdx.x;
    int uj = u & 63;
    const float* __restrict__ Gb = g_G + (size_t)b * LQ * LQ;
    const float4* __restrict__ r04 = (const float4*)(Gb + (size_t)u * LQ);
    const float4* __restrict__ rm4 = (const float4*)(Gb + (size_t)(u - 1) * LQ);
    const float4* __restrict__ rp4 = (const float4*)(Gb + (size_t)(u + 1) * LQ);
    const float* __restrict__ rmf = Gb + (size_t)(u - 1) * LQ;
    const float* __restrict__ rpf = Gb + (size_t)(u + 1) * LQ;
    float4* __restrict__ Tu = (float4*)(g_T + (size_t)b * LQ * LQ + (size_t)u * LQ);
    bool um = (uj > 0), up = (uj < 63);

    for (int i = threadIdx.x; i < 1024; i += 256) {
        int v = i * 4;
        float4 o = __ldg(r04 + i);
        if (um) {
            float4 m = __ldg(rm4 + i);
            if (v & 63) o.x += __ldg(rmf + v - 1);
            o.y += m.x; o.z += m.y; o.w += m.z;
        }
        if (up) {
            float4 pq = __ldg(rp4 + i);
            o.x += pq.y; o.y += pq.z; o.z += pq.w;
            if ((v & 63) != 60) o.w += __ldg(rpf + v + 4);
        }
        Tu[i] = o;
    }
}

// ===================================================================
// Kernel 3c: pass2 (i-diagonal) + inv scale, float4 (R13 config):
// att[p][q] = (T[p][q] + T[p-64][q-64](pi>0,qi>0)
//              + T[p+64][q+64](pi<63,qi<63)) * inv[q]
// ===================================================================
__global__ void __launch_bounds__(256) diag2_kernel(float* __restrict__ out)
{
    int b = blockIdx.y;
    int p = blockIdx.x;
    int pi = p >> 6;
    const float* __restrict__ Tb = g_T + (size_t)b * LQ * LQ;
    const float4* __restrict__ r04 = (const float4*)(Tb + (size_t)p * LQ);
    const float4* __restrict__ rm4 = (const float4*)(Tb + (size_t)(p - 64) * LQ);
    const float4* __restrict__ rp4 = (const float4*)(Tb + (size_t)(p + 64) * LQ);
    const float4* __restrict__ inv4 = (const float4*)(g_invden + b * LQ);
    float4* __restrict__ orow = (float4*)(out + YSZ + (size_t)b * LQ * LQ + (size_t)p * LQ);
    bool um = (pi > 0), up = (pi < 63);

    for (int i = threadIdx.x; i < 1024; i += 256) {
        int qi = i >> 4;
        float4 o = __ldg(r04 + i);
        if (um && qi > 0) {
            float4 m = __ldg(rm4 + i - 16);
            o.x += m.x; o.y += m.y; o.z += m.z; o.w += m.w;
        }
        if (up && qi < 63) {
            float4 pq = __ldg(rp4 + i + 16);
            o.x += pq.x; o.y += pq.y; o.z += pq.z; o.w += pq.w;
        }
        float4 iv = __ldg(inv4 + i);
        o.x *= iv.x; o.y *= iv.y; o.z *= iv.z; o.w *= iv.w;
        orow[i] = o;
    }
}

// ===================================================================
// Kernel 4: fuse + stable softmax -> split-fp16 U (8 p per block)
// ===================================================================
__global__ void __launch_bounds__(256) fuse_softmax_kernel(const float* __restrict__ out)
{
    int b = blockIdx.y;
    int bx = blockIdx.x;
    int qj = bx & 63;
    int qi0 = (bx >> 6) << 3;

    const float* __restrict__ ab = out + YSZ + (size_t)b * LQ * LQ;
    const int* __restrict__ idxb = g_idx + b * LQ;

    int cnt = g_cnt[b * 2 + 0];
    int pad = g_cnt[b * 2 + 1];

    __shared__ float zbuf[LQ];
    __shared__ float red[256];

    int t = threadIdx.x;

    for (int sub = 0; sub < 8; sub++) {
        int qi = qi0 + sub;
        int p = (qi << 6) | qj;
        int ap = (qj << 6) | qi;
        __half* __restrict__ Uhp = g_Uhi + ((size_t)b * LQ + p) * LQ;
        __half* __restrict__ Ulp = g_Ulo + ((size_t)b * LQ + p) * LQ;

        float lmax = (cnt < LQ) ? 0.0f : -3.4e38f;

        for (int j = t; j < pad; j += 256) {
            float z = 0.0f;
            if (j < cnt) {
                int l = __ldg(idxb + j);
                int ki = l >> 6, kj = l & 63;
                int bp = (kj << 6) | ki;
                float acc = 0.0f;
#pragma unroll
                for (int d2 = -1; d2 <= 1; d2++) {
                    int aa = ap + d2;
                    int bb = bp + d2;
                    if ((unsigned)aa < LQ && (unsigned)bb < LQ) {
                        int u0 = ((aa & 63) << 6) | (aa >> 6);
                        int v0 = ((bb & 63) << 6) | (bb >> 6);
#pragma unroll
                        for (int d1 = -1; d1 <= 1; d1++) {
                            int uu = u0 + d1, vv = v0 + d1;
                            if ((unsigned)uu < LQ && (unsigned)vv < LQ)
                                acc += __ldg(ab + (size_t)uu * LQ + vv);
                        }
                    }
                }
                z = acc * 10.0f;
                lmax = fmaxf(lmax, z);
            }
            zbuf[j] = z;
        }

        red[t] = lmax;
        __syncthreads();
        for (int off = 128; off >= 1; off >>= 1) {
            if (t < off) red[t] = fmaxf(red[t], red[t + off]);
            __syncthreads();
        }
        float rmax = red[0];
        __syncthreads();

        float lsum = 0.0f;
        for (int j = t; j < pad; j += 256) {
            float e = 0.0f;
            if (j < cnt) {
                e = expf(zbuf[j] - rmax);
                lsum += e;
            }
            zbuf[j] = e;
        }
        red[t] = lsum;
        __syncthreads();
        for (int off = 128; off >= 1; off >>= 1) {
            if (t < off) red[t] += red[t + off];
            __syncthreads();
        }
        float den = red[0] + (float)(LQ - cnt) * expf(-rmax);
        float invs = 1.0f / den;
        __syncthreads();

        for (int j = t; j < pad; j += 256) {
            float val = zbuf[j] * invs;
            __half hi = __float2half(val);
            Uhp[j] = hi;
            Ulp[j] = __float2half(val - __half2float(hi));
        }
        __syncthreads();
    }
}

// ===================================================================
// Kernel 5: recon GEMM via fp16 mma.sync, 2-combo:
// Z = (Uhi + Ulo) @ fp16(V)^T. 128x96 tile, warp 64x24, BK=16,
// 4-stage ring, 2 CTAs/SM.
// ===================================================================
#define ZTA 4096
#define ZTB 3072
#define ZBUF (2 * ZTA + ZTB)

__global__ void __launch_bounds__(256, 2) gemm_z_mma_kernel()
{
    __shared__ __align__(16) unsigned char smem_raw[4 * ZBUF];  // 44KB

    int t = threadIdx.x;
    int lane = t & 31;
    int wid = t >> 5;
    int warp_m = wid >> 2;
    int warp_n = wid & 3;
    int b = blockIdx.z;
    int p0 = blockIdx.y * 128;
    int n0 = blockIdx.x * 96;

    int kmax = g_cnt[b * 2 + 1];
    int NIT = kmax >> 4;

    uint32_t sbase = smem_u32(smem_raw);
    const char* Ah = (const char*)(g_Uhi + ((size_t)b * LQ + p0) * LQ);
    const char* Al = (const char*)(g_Ulo + ((size_t)b * LQ + p0) * LQ);
    const char* Bh = (const char*)(g_VT + ((size_t)b * KC + n0) * LQ);

    float acc[4][3][4];
#pragma unroll
    for (int i = 0; i < 4; i++)
#pragma unroll
        for (int j = 0; j < 3; j++)
#pragma unroll
            for (int k = 0; k < 4; k++) acc[i][j][k] = 0.0f;

    auto stage = [&](int buf, int kc) {
        uint32_t sdst = sbase + buf * ZBUF;
        size_t col = (size_t)kc * 32;
        for (int i = t; i < 704; i += 256) {
            if (i < 512) {
                const char* src = (i < 256) ? Ah : Al;
                uint32_t base = sdst + ((i < 256) ? 0 : ZTA);
                int rid = i & 255;
                int row = rid >> 1, u = rid & 1;
                cp16(base + sw32(row, u), src + (size_t)row * (LQ * 2) + col + u * 16);
            } else {
                int j = i - 512;
                int row = j >> 1, u = j & 1;
                cp16(sdst + 2 * ZTA + sw32(row, u), Bh + (size_t)row * (LQ * 2) + col + u * 16);
            }
        }
    };

    int lr = lane & 7, sel = lane >> 3;
    int half2 = (lane >> 3) & 1;
    auto compute = [&](int buf) {
        uint32_t sAh = sbase + buf * ZBUF;
        uint32_t sAl = sAh + ZTA;
        uint32_t sBh = sAh + 2 * ZTA;

        uint32_t ah[4][4], al[4][4];
#pragma unroll
        for (int mt = 0; mt < 4; mt++) {
            int row = warp_m * 64 + mt * 16 + lr + (sel & 1) * 8;
            int cc = sel >> 1;
            ldsm4(sAh + sw32(row, cc), ah[mt][0], ah[mt][1], ah[mt][2], ah[mt][3]);
            ldsm4(sAl + sw32(row, cc), al[mt][0], al[mt][1], al[mt][2], al[mt][3]);
        }
        uint32_t bh[6];
        {
            int row = warp_n * 24 + lr + (sel >> 1) * 8;
            int cc = sel & 1;
            ldsm4(sBh + sw32(row, cc), bh[0], bh[1], bh[2], bh[3]);
        }
        {
            int row = warp_n * 24 + 16 + lr;
            int cc = half2;
            ldsm2(sBh + sw32(row, cc), bh[4], bh[5]);
        }
#pragma unroll
        for (int mt = 0; mt < 4; mt++)
#pragma unroll
            for (int nt = 0; nt < 3; nt++) {
                mma16816h(acc[mt][nt][0], acc[mt][nt][1], acc[mt][nt][2], acc[mt][nt][3],
                          ah[mt][0], ah[mt][1], ah[mt][2], ah[mt][3], bh[nt * 2], bh[nt * 2 + 1]);
                mma16816h(acc[mt][nt][0], acc[mt][nt][1], acc[mt][nt][2], acc[mt][nt][3],
                          al[mt][0], al[mt][1], al[mt][2], al[mt][3], bh[nt * 2], bh[nt * 2 + 1]);
            }
    };

    stage(0, 0); cp_commit();
    stage(1, 1); cp_commit();
    for (int it = 0; it < NIT; it++) {
        if (it + 2 < NIT) {
            stage((it + 2) & 3, it + 2);
            cp_commit();
            cp_wait<2>();
        } else if (it + 1 < NIT) {
            cp_wait<1>();
        } else {
            cp_wait<0>();
        }
        __syncthreads();
        compute(it & 3);
    }

    float* __restrict__ Zb = g_Z + (size_t)b * LQ * KC;
    int r0l = lane >> 2;
    int c0l = (lane & 3) * 2;
#pragma unroll
    for (int mt = 0; mt < 4; mt++)
#pragma unroll
        for (int nt = 0; nt < 3; nt++) {
            int row = p0 + warp_m * 64 + mt * 16 + r0l;
            int col = n0 + warp_n * 24 + nt * 8 + c0l;
            *(float2*)(Zb + (size_t)row * KC + col) =
                make_float2(acc[mt][nt][0], acc[mt][nt][1]);
            *(float2*)(Zb + (size_t)(row + 8) * KC + col) =
                make_float2(acc[mt][nt][2], acc[mt][nt][3]);
        }
}

// ===================================================================
// Kernel 6: overlap-add (transposed conv gather), float4 per thread
// ===================================================================
__global__ void recon_kernel(float* __restrict__ out)
{
    int idx = blockIdx.x * blockDim.x + threadIdx.x;
    if (idx >= (int)(YSZ / 4)) return;
    int c4 = (idx & 15) * 4;
    int tmp = idx >> 4;
    int J = tmp & 127; tmp >>= 7;
    int I = tmp & 127;
    int b = tmp >> 7;

    int ri[2], rdh[2], rn = 0;
    if (I & 1) { ri[0] = (I - 1) >> 1; rdh[0] = 1; rn = 1; }
    else {
        ri[rn] = I >> 1; rdh[rn] = 0; rn++;
        if (I >= 2) { ri[rn] = (I >> 1) - 1; rdh[rn] = 2; rn++; }
    }
    int cj[2], cdw[2], cn = 0;
    if (J & 1) { cj[0] = (J - 1) >> 1; cdw[0] = 1; cn = 1; }
    else {
        cj[cn] = J >> 1; cdw[cn] = 0; cn++;
        if (J >= 2) { cj[cn] = (J >> 1) - 1; cdw[cn] = 2; cn++; }
    }

    const float* __restrict__ Zb = g_Z + (size_t)b * LQ * KC;
    float4 acc = make_float4(0.f, 0.f, 0.f, 0.f);
    for (int a = 0; a < rn; a++) {
        for (int bb = 0; bb < cn; bb++) {
            int l = ri[a] * 64 + cj[bb];
            int n = (rdh[a] * 3 + cdw[bb]) * 64 + c4;
            float4 v = *(const float4*)(Zb + (size_t)l * KC + n);
            acc.x += v.x; acc.y += v.y; acc.z += v.z; acc.w += v.w;
        }
    }
    acc.x *= 0.25f; acc.y *= 0.25f; acc.z *= 0.25f; acc.w *= 0.25f;
    size_t o = (((size_t)b * HFULL + I) * WFULL + J) * CCH + c4;
    *(float4*)(out + o) = acc;
}

// ===================================================================
extern "C" void kernel_launch(void* const* d_in, const int* in_sizes, int n_in,
                              void* d_out, int out_size)
{
    const float* x    = (const float*)d_in[0];
    const float* mask = (const float*)d_in[1];
    float* out = (float*)d_out;
    (void)in_sizes; (void)n_in; (void)out_size;

    build_f_kernel<<<dim3(LQ / 4, BATCH), 256>>>(x);
    mm_invden_kernel<<<(BATCH * LQ + 255) / 256, 256>>>(mask);
    compact_kernel<<<BATCH, 1024>>>();
    vcompT_kernel<<<dim3(KC, BATCH), 256>>>(x);
    gemm_g_kernel<<<dim3(32, 32, BATCH), 512>>>();
    diag1_kernel<<<dim3(LQ, BATCH), 256>>>();
    diag2_kernel<<<dim3(LQ, BATCH), 256>>>(out);
    fuse_softmax_kernel<<<dim3(512, BATCH), 256>>>(out);
    gemm_z_mma_kernel<<<dim3(6, 32, BATCH), 256>>>();
    recon_kernel<<<(int)(YSZ / 4 + 255) / 256, 256>>>(out);
}

// round 17
// speedup vs baseline: 1.1194x; 1.0284x over previous
#include <cuda_runtime.h>
#include <cuda_fp16.h>
#include <cstdint>

// Problem constants
#define BATCH 2
#define HFULL 128
#define WFULL 128
#define CCH   64
#define HLO   64
#define WLO   64
#define LQ    4096          // HLO*WLO
#define KC    576           // 3*3*CCH

static const size_t YSZ = (size_t)BATCH * HFULL * WFULL * CCH; // y output floats

// -------- static device scratch --------
__device__ __align__(16) __half g_Fhf[(size_t)BATCH * LQ * 128]; // f as [hi(64)|lo(64)] per pixel
__device__ float g_n2[BATCH * LQ];                               // ||f_l||^2
__device__ float g_G[(size_t)BATCH * LQ * LQ];                   // Gram of f (C=64 dots)
__device__ float g_T[(size_t)BATCH * LQ * LQ];                   // j-diagonal partial sums
__device__ float g_Z[(size_t)BATCH * LQ * KC];
__device__ __align__(16) __half g_Uhi[(size_t)BATCH * LQ * LQ];
__device__ __align__(16) __half g_Ulo[(size_t)BATCH * LQ * LQ];
__device__ __align__(16) __half g_VT[(size_t)BATCH * KC * LQ];   // [n][j] fp16-quantized
__device__ float g_invden[BATCH * LQ];
__device__ float g_mm[BATCH * LQ];
__device__ int   g_idx[BATCH * LQ];
__device__ int   g_cnt[BATCH * 2];

// ---------------- helpers ----------------
__device__ __forceinline__ uint32_t smem_u32(const void* p) {
    uint32_t a;
    asm("{ .reg .u64 t; cvta.to.shared.u64 t, %1; cvt.u32.u64 %0, t; }" : "=r"(a) : "l"(p));
    return a;
}
__device__ __forceinline__ void cp16(uint32_t dst, const void* src) {
    asm volatile("cp.async.cg.shared.global [%0], [%1], 16;" :: "r"(dst), "l"(src));
}
__device__ __forceinline__ void cp_commit() {
    asm volatile("cp.async.commit_group;");
}
template<int N> __device__ __forceinline__ void cp_wait() {
    asm volatile("cp.async.wait_group %0;" :: "n"(N));
}
__device__ __forceinline__ void ldsm4(uint32_t a, uint32_t& r0, uint32_t& r1, uint32_t& r2, uint32_t& r3) {
    asm volatile("ldmatrix.sync.aligned.m8n8.x4.shared.b16 {%0,%1,%2,%3}, [%4];"
                 : "=r"(r0), "=r"(r1), "=r"(r2), "=r"(r3) : "r"(a));
}
__device__ __forceinline__ void ldsm2(uint32_t a, uint32_t& r0, uint32_t& r1) {
    asm volatile("ldmatrix.sync.aligned.m8n8.x2.shared.b16 {%0,%1}, [%2];"
                 : "=r"(r0), "=r"(r1) : "r"(a));
}
__device__ __forceinline__ void mma16816h(float& c0, float& c1, float& c2, float& c3,
                                          uint32_t a0, uint32_t a1, uint32_t a2, uint32_t a3,
                                          uint32_t b0, uint32_t b1) {
    asm volatile("mma.sync.aligned.m16n8k16.row.col.f32.f16.f16.f32 "
                 "{%0,%1,%2,%3}, {%4,%5,%6,%7}, {%8,%9}, {%0,%1,%2,%3};"
                 : "+f"(c0), "+f"(c1), "+f"(c2), "+f"(c3)
                 : "r"(a0), "r"(a1), "r"(a2), "r"(a3), "r"(b0), "r"(b1));
}
__device__ __forceinline__ uint32_t sw32(int row, int chunk) {
    return (uint32_t)(row * 32 + 16 * (chunk ^ ((row >> 2) & 1)));
}

// ===================================================================
// Kernel 1: build split-fp16 f (avgpool) + per-pixel channel norm^2
// ===================================================================
__global__ void __launch_bounds__(256) build_f_kernel(const float* __restrict__ x)
{
    int b = blockIdx.y;
    int l = blockIdx.x * 4 + (threadIdx.x >> 6);
    int c = threadIdx.x & 63;
    int li = l >> 6, lj = l & 63;

    const size_t xb = (size_t)b * HFULL * WFULL * CCH;
    size_t base = xb + (size_t)(2 * li) * (WFULL * CCH) + (size_t)(2 * lj) * CCH + c;
    float pv = 0.25f * (x[base] + x[base + CCH] + x[base + WFULL * CCH] + x[base + WFULL * CCH + CCH]);

    __half hi = __float2half(pv);
    __half lo = __float2half(pv - __half2float(hi));
    size_t rb = ((size_t)b * LQ + l) * 128;
    g_Fhf[rb + c]      = hi;
    g_Fhf[rb + 64 + c] = lo;

    float sq = pv * pv;
#pragma unroll
    for (int off = 16; off >= 1; off >>= 1)
        sq += __shfl_xor_sync(0xffffffffu, sq, off);
    __shared__ float ws[8];
    int warp = threadIdx.x >> 5;
    if ((threadIdx.x & 31) == 0) ws[warp] = sq;
    __syncthreads();
    if ((threadIdx.x & 63) == 0)
        g_n2[b * LQ + l] = ws[warp] + ws[warp + 1];
}

// ===================================================================
// Kernel 2: mask gate + invden merged (same 3x3 validity loop)
// ===================================================================
__global__ void mm_invden_kernel(const float* __restrict__ mask)
{
    int idx = blockIdx.x * blockDim.x + threadIdx.x;
    if (idx >= BATCH * LQ) return;
    int b = idx / LQ;
    int l = idx % LQ;
    int li = l >> 6, lj = l & 63;
    const size_t mb = (size_t)b * HFULL * WFULL;

    float sum9 = 0.0f;
    float sn = 0.0f;
    for (int dh = 0; dh < 3; dh++) {
        for (int dw = 0; dw < 3; dw++) {
            int fi = li - 1 + dh, fj = lj - 1 + dw;
            if (fi >= 0 && fi < HLO && fj >= 0 && fj < WLO) {
                size_t base = mb + (size_t)(2 * fi) * WFULL + (2 * fj);
                sum9 += 0.25f * (mask[base] + mask[base + 1] + mask[base + WFULL] + mask[base + WFULL + 1]);
                sn += g_n2[b * LQ + (fi << 6) + fj];
            }
        }
    }
    float mean = sum9 / 9.0f;
    g_mm[idx] = (mean == 1.0f) ? 1.0f : 0.0f;
    g_invden[idx] = 1.0f / fmaxf(sqrtf(sn), 1e-4f);
}

// ===================================================================
// Kernel 2b: deterministic compaction of active columns (pad to 64)
// ===================================================================
__global__ void __launch_bounds__(1024) compact_kernel()
{
    int b = blockIdx.x;
    int t = threadIdx.x;
    __shared__ int sc[1024];

    int base = t * 4;
    int loc[4];
    int cnt = 0;
#pragma unroll
    for (int i = 0; i < 4; i++) {
        loc[i] = (g_mm[b * LQ + base + i] != 0.0f) ? 1 : 0;
        cnt += loc[i];
    }
    sc[t] = cnt;
    __syncthreads();
    for (int off = 1; off < 1024; off <<= 1) {
        int v = (t >= off) ? sc[t - off] : 0;
        __syncthreads();
        sc[t] += v;
        __syncthreads();
    }
    int pos = sc[t] - cnt;
#pragma unroll
    for (int i = 0; i < 4; i++) {
        if (loc[i]) g_idx[b * LQ + (pos++)] = base + i;
    }
    if (t == 1023) {
        int total = sc[1023];
        int pad = (total + 63) & ~63;
        g_cnt[b * 2 + 0] = total;
        g_cnt[b * 2 + 1] = pad;
        for (int j = total; j < pad; j++) g_idx[b * LQ + j] = 0;
    }
}

// ===================================================================
// Kernel 2c: compacted-transposed fp16 V read straight from x
// ===================================================================
__global__ void __launch_bounds__(256) vcompT_kernel(const float* __restrict__ x)
{
    int b = blockIdx.y;
    int n = blockIdx.x;
    int g = n >> 6;
    int c = n & 63;
    int dh = g / 3, dw = g % 3;
    int cnt = g_cnt[b * 2 + 0];
    int pad = g_cnt[b * 2 + 1];
    const int* __restrict__ idxb = g_idx + b * LQ;
    const float* __restrict__ xb = x + (size_t)b * HFULL * WFULL * CCH;
    __half* __restrict__ Vn = g_VT + ((size_t)b * KC + n) * LQ;

    for (int j = threadIdx.x; j < pad; j += 256) {
        float v = 0.0f;
        if (j < cnt) {
            int l = __ldg(idxb + j);
            int xr = 2 * (l >> 6) + dh;
            int xc = 2 * (l & 63) + dw;
            if (xr < HFULL && xc < WFULL)
                v = __ldg(xb + (size_t)xr * (WFULL * CCH) + (size_t)xc * CCH + c);
        }
        Vn[j] = __float2half(v);
    }
}

// ===================================================================
// Kernel 3a: Gram GEMM G[u][v] = f_u . f_v (K=64) via fp16 3-combo
// float4 epilogue stores.
// ===================================================================
#define STILE 4096
#define SBUF  (4 * STILE)

__global__ void __launch_bounds__(512) gemm_g_kernel()
{
    if (blockIdx.x < blockIdx.y) return;

    __shared__ __align__(16) unsigned char smem_raw[3 * SBUF];  // 48KB

    int t = threadIdx.x;
    int lane = t & 31;
    int wid = t >> 5;
    int warp_m = wid >> 2;
    int warp_n = wid & 3;
    int b = blockIdx.z;
    int p0 = blockIdx.y * 128;
    int q0 = blockIdx.x * 128;

    uint32_t sbase = smem_u32(smem_raw);
    const char* Abase = (const char*)g_Fhf + ((size_t)b * LQ + p0) * 256;
    const char* Bbase = (const char*)g_Fhf + ((size_t)b * LQ + q0) * 256;

    float acc[2][4][4];
#pragma unroll
    for (int i = 0; i < 2; i++)
#pragma unroll
        for (int j = 0; j < 4; j++)
#pragma unroll
            for (int k = 0; k < 4; k++) acc[i][j][k] = 0.0f;

    const int NIT = 4;
    auto stage = [&](int buf, int kc) {
        uint32_t sdst = sbase + buf * SBUF;
        size_t col = (size_t)kc * 32;
#pragma unroll
        for (int r = 0; r < 2; r++) {
            int id = r * 512 + t;
            int tile = id >> 8;
            int rid = id & 255;
            int row = rid >> 1, u = rid & 1;
            const char* src = (tile < 2 ? Abase : Bbase)
                            + (size_t)row * 256 + col
                            + ((tile & 1) ? 128 : 0)
                            + u * 16;
            cp16(sdst + tile * STILE + sw32(row, u), src);
        }
    };

    int lr = lane & 7, sel = lane >> 3;
    auto compute = [&](int buf) {
        uint32_t sAhi = sbase + buf * SBUF;
        uint32_t sAlo = sAhi + STILE;
        uint32_t sBhi = sAhi + 2 * STILE;
        uint32_t sBlo = sAhi + 3 * STILE;

        uint32_t ah[2][4], al[2][4];
#pragma unroll
        for (int mt = 0; mt < 2; mt++) {
            int row = warp_m * 32 + mt * 16 + lr + (sel & 1) * 8;
            int cc = sel >> 1;
            ldsm4(sAhi + sw32(row, cc), ah[mt][0], ah[mt][1], ah[mt][2], ah[mt][3]);
            ldsm4(sAlo + sw32(row, cc), al[mt][0], al[mt][1], al[mt][2], al[mt][3]);
        }
        uint32_t bh[2][4], bl[2][4];
#pragma unroll
        for (int ntp = 0; ntp < 2; ntp++) {
            int row = warp_n * 32 + ntp * 16 + lr + (sel >> 1) * 8;
            int cc = sel & 1;
            ldsm4(sBhi + sw32(row, cc), bh[ntp][0], bh[ntp][1], bh[ntp][2], bh[ntp][3]);
            ldsm4(sBlo + sw32(row, cc), bl[ntp][0], bl[ntp][1], bl[ntp][2], bl[ntp][3]);
        }
#pragma unroll
        for (int mt = 0; mt < 2; mt++)
#pragma unroll
            for (int nt = 0; nt < 4; nt++) {
                int g = nt >> 1, h = (nt & 1) * 2;
                mma16816h(acc[mt][nt][0], acc[mt][nt][1], acc[mt][nt][2], acc[mt][nt][3],
                          ah[mt][0], ah[mt][1], ah[mt][2], ah[mt][3], bh[g][h], bh[g][h + 1]);
                mma16816h(acc[mt][nt][0], acc[mt][nt][1], acc[mt][nt][2], acc[mt][nt][3],
                          ah[mt][0], ah[mt][1], ah[mt][2], ah[mt][3], bl[g][h], bl[g][h + 1]);
                mma16816h(acc[mt][nt][0], acc[mt][nt][1], acc[mt][nt][2], acc[mt][nt][3],
                          al[mt][0], al[mt][1], al[mt][2], al[mt][3], bh[g][h], bh[g][h + 1]);
            }
    };

    stage(0, 0);
    cp_commit();
    for (int it = 0; it < NIT; it++) {
        if (it + 1 < NIT) {
            stage((it + 1) % 3, it + 1);
            cp_commit();
            cp_wait<1>();
        } else {
            cp_wait<0>();
        }
        __syncthreads();
        compute(it % 3);
    }

    float* __restrict__ Gb = g_G + (size_t)b * LQ * LQ;
    float* S = (float*)smem_raw;

#pragma unroll
    for (int mhalf = 0; mhalf < 2; mhalf++) {
        __syncthreads();
        if ((warp_m >> 1) == mhalf) {
            int r0l = lane >> 2;
            int c0l = (lane & 3) * 2;
#pragma unroll
            for (int mt = 0; mt < 2; mt++)
#pragma unroll
                for (int nt = 0; nt < 4; nt++) {
                    int rr = (warp_m & 1) * 32 + mt * 16 + r0l;
                    int cc = warp_n * 32 + nt * 8 + c0l;
                    S[rr * 132 + cc]           = acc[mt][nt][0];
                    S[rr * 132 + cc + 1]       = acc[mt][nt][1];
                    S[(rr + 8) * 132 + cc]     = acc[mt][nt][2];
                    S[(rr + 8) * 132 + cc + 1] = acc[mt][nt][3];
                }
        }
        __syncthreads();
        // normal half: float4 stores
        {
            int r = t >> 3, cs = (t & 7) * 16;
            float4* dst = (float4*)(Gb + (size_t)(p0 + mhalf * 64 + r) * LQ + q0 + cs);
            const float* sp = S + r * 132 + cs;
#pragma unroll
            for (int j = 0; j < 4; j++)
                dst[j] = *(const float4*)(sp + j * 4);
        }
        // mirrored half: float4 stores along p
        {
            int c = t >> 2, rs = (t & 3) * 16;
            float* dst = Gb + (size_t)(q0 + c) * LQ + p0 + mhalf * 64 + rs;
#pragma unroll
            for (int j = 0; j < 4; j++) {
                float4 w = make_float4(S[(rs + 4 * j) * 132 + c],
                                       S[(rs + 4 * j + 1) * 132 + c],
                                       S[(rs + 4 * j + 2) * 132 + c],
                                       S[(rs + 4 * j + 3) * 132 + c]);
                *(float4*)(dst + 4 * j) = w;
            }
        }
    }
}

// ===================================================================
// Kernel 3b: pass1 (j-diagonal), float4 vectorized (R13 config):
// T[u][v] = G[u][v] + G[u-1][v-1](uj>0,vj>0) + G[u+1][v+1](uj<63,vj<63)
// ===================================================================
__global__ void __launch_bounds__(256) diag1_kernel()
{
    int b = blockIdx.y;
    int u = blockIdx.x;
    int uj = u & 63;
    const float* __restrict__ Gb = g_G + (size_t)b * LQ * LQ;
    const float4* __restrict__ r04 = (const float4*)(Gb + (size_t)u * LQ);
    const float4* __restrict__ rm4 = (const float4*)(Gb + (size_t)(u - 1) * LQ);
    const float4* __restrict__ rp4 = (const float4*)(Gb + (size_t)(u + 1) * LQ);
    const float* __restrict__ rmf = Gb + (size_t)(u - 1) * LQ;
    const float* __restrict__ rpf = Gb + (size_t)(u + 1) * LQ;
    float4* __restrict__ Tu = (float4*)(g_T + (size_t)b * LQ * LQ + (size_t)u * LQ);
    bool um = (uj > 0), up = (uj < 63);

    for (int i = threadIdx.x; i < 1024; i += 256) {
        int v = i * 4;
        float4 o = __ldg(r04 + i);
        if (um) {
            float4 m = __ldg(rm4 + i);
            if (v & 63) o.x += __ldg(rmf + v - 1);
            o.y += m.x; o.z += m.y; o.w += m.z;
        }
        if (up) {
            float4 pq = __ldg(rp4 + i);
            o.x += pq.y; o.y += pq.z; o.z += pq.w;
            if ((v & 63) != 60) o.w += __ldg(rpf + v + 4);
        }
        Tu[i] = o;
    }
}

// ===================================================================
// Kernel 3c: pass2 (i-diagonal) + inv scale, float4 (R13 config):
// att[p][q] = (T[p][q] + T[p-64][q-64](pi>0,qi>0)
//              + T[p+64][q+64](pi<63,qi<63)) * inv[q]
// ===================================================================
__global__ void __launch_bounds__(256) diag2_kernel(float* __restrict__ out)
{
    int b = blockIdx.y;
    int p = blockIdx.x;
    int pi = p >> 6;
    const float* __restrict__ Tb = g_T + (size_t)b * LQ * LQ;
    const float4* __restrict__ r04 = (const float4*)(Tb + (size_t)p * LQ);
    const float4* __restrict__ rm4 = (const float4*)(Tb + (size_t)(p - 64) * LQ);
    const float4* __restrict__ rp4 = (const float4*)(Tb + (size_t)(p + 64) * LQ);
    const float4* __restrict__ inv4 = (const float4*)(g_invden + b * LQ);
    float4* __restrict__ orow = (float4*)(out + YSZ + (size_t)b * LQ * LQ + (size_t)p * LQ);
    bool um = (pi > 0), up = (pi < 63);

    for (int i = threadIdx.x; i < 1024; i += 256) {
        int qi = i >> 4;
        float4 o = __ldg(r04 + i);
        if (um && qi > 0) {
            float4 m = __ldg(rm4 + i - 16);
            o.x += m.x; o.y += m.y; o.z += m.z; o.w += m.w;
        }
        if (up && qi < 63) {
            float4 pq = __ldg(rp4 + i + 16);
            o.x += pq.x; o.y += pq.y; o.z += pq.z; o.w += pq.w;
        }
        float4 iv = __ldg(inv4 + i);
        o.x *= iv.x; o.y *= iv.y; o.z *= iv.z; o.w *= iv.w;
        orow[i] = o;
    }
}

// ===================================================================
// Kernel 4: fuse + stable softmax -> split-fp16 U (8 p per block)
// ===================================================================
__global__ void __launch_bounds__(256) fuse_softmax_kernel(const float* __restrict__ out)
{
    int b = blockIdx.y;
    int bx = blockIdx.x;
    int qj = bx & 63;
    int qi0 = (bx >> 6) << 3;

    const float* __restrict__ ab = out + YSZ + (size_t)b * LQ * LQ;
    const int* __restrict__ idxb = g_idx + b * LQ;

    int cnt = g_cnt[b * 2 + 0];
    int pad = g_cnt[b * 2 + 1];

    __shared__ float zbuf[LQ];
    __shared__ float red[256];

    int t = threadIdx.x;

    for (int sub = 0; sub < 8; sub++) {
        int qi = qi0 + sub;
        int p = (qi << 6) | qj;
        int ap = (qj << 6) | qi;
        __half* __restrict__ Uhp = g_Uhi + ((size_t)b * LQ + p) * LQ;
        __half* __restrict__ Ulp = g_Ulo + ((size_t)b * LQ + p) * LQ;

        float lmax = (cnt < LQ) ? 0.0f : -3.4e38f;

        for (int j = t; j < pad; j += 256) {
            float z = 0.0f;
            if (j < cnt) {
                int l = __ldg(idxb + j);
                int ki = l >> 6, kj = l & 63;
                int bp = (kj << 6) | ki;
                float acc = 0.0f;
#pragma unroll
                for (int d2 = -1; d2 <= 1; d2++) {
                    int aa = ap + d2;
                    int bb = bp + d2;
                    if ((unsigned)aa < LQ && (unsigned)bb < LQ) {
                        int u0 = ((aa & 63) << 6) | (aa >> 6);
                        int v0 = ((bb & 63) << 6) | (bb >> 6);
#pragma unroll
                        for (int d1 = -1; d1 <= 1; d1++) {
                            int uu = u0 + d1, vv = v0 + d1;
                            if ((unsigned)uu < LQ && (unsigned)vv < LQ)
                                acc += __ldg(ab + (size_t)uu * LQ + vv);
                        }
                    }
                }
                z = acc * 10.0f;
                lmax = fmaxf(lmax, z);
            }
            zbuf[j] = z;
        }

        red[t] = lmax;
        __syncthreads();
        for (int off = 128; off >= 1; off >>= 1) {
            if (t < off) red[t] = fmaxf(red[t], red[t + off]);
            __syncthreads();
        }
        float rmax = red[0];
        __syncthreads();

        float lsum = 0.0f;
        for (int j = t; j < pad; j += 256) {
            float e = 0.0f;
            if (j < cnt) {
                e = expf(zbuf[j] - rmax);
                lsum += e;
            }
            zbuf[j] = e;
        }
        red[t] = lsum;
        __syncthreads();
        for (int off = 128; off >= 1; off >>= 1) {
            if (t < off) red[t] += red[t + off];
            __syncthreads();
        }
        float den = red[0] + (float)(LQ - cnt) * expf(-rmax);
        float invs = 1.0f / den;
        __syncthreads();

        for (int j = t; j < pad; j += 256) {
            float val = zbuf[j] * invs;
            __half hi = __float2half(val);
            Uhp[j] = hi;
            Ulp[j] = __float2half(val - __half2float(hi));
        }
        __syncthreads();
    }
}

// ===================================================================
// Kernel 5: recon GEMM via fp16 mma.sync, 2-combo:
// Z = (Uhi + Ulo) @ fp16(V)^T. 128x96 tile, warp 64x24, BK=16,
// 4-stage ring, 2 CTAs/SM.
// ===================================================================
#define ZTA 4096
#define ZTB 3072
#define ZBUF (2 * ZTA + ZTB)

__global__ void __launch_bounds__(256, 2) gemm_z_mma_kernel()
{
    __shared__ __align__(16) unsigned char smem_raw[4 * ZBUF];  // 44KB

    int t = threadIdx.x;
    int lane = t & 31;
    int wid = t >> 5;
    int warp_m = wid >> 2;
    int warp_n = wid & 3;
    int b = blockIdx.z;
    int p0 = blockIdx.y * 128;
    int n0 = blockIdx.x * 96;

    int kmax = g_cnt[b * 2 + 1];
    int NIT = kmax >> 4;

    uint32_t sbase = smem_u32(smem_raw);
    const char* Ah = (const char*)(g_Uhi + ((size_t)b * LQ + p0) * LQ);
    const char* Al = (const char*)(g_Ulo + ((size_t)b * LQ + p0) * LQ);
    const char* Bh = (const char*)(g_VT + ((size_t)b * KC + n0) * LQ);

    float acc[4][3][4];
#pragma unroll
    for (int i = 0; i < 4; i++)
#pragma unroll
        for (int j = 0; j < 3; j++)
#pragma unroll
            for (int k = 0; k < 4; k++) acc[i][j][k] = 0.0f;

    auto stage = [&](int buf, int kc) {
        uint32_t sdst = sbase + buf * ZBUF;
        size_t col = (size_t)kc * 32;
        for (int i = t; i < 704; i += 256) {
            if (i < 512) {
                const char* src = (i < 256) ? Ah : Al;
                uint32_t base = sdst + ((i < 256) ? 0 : ZTA);
                int rid = i & 255;
                int row = rid >> 1, u = rid & 1;
                cp16(base + sw32(row, u), src + (size_t)row * (LQ * 2) + col + u * 16);
            } else {
                int j = i - 512;
                int row = j >> 1, u = j & 1;
                cp16(sdst + 2 * ZTA + sw32(row, u), Bh + (size_t)row * (LQ * 2) + col + u * 16);
            }
        }
    };

    int lr = lane & 7, sel = lane >> 3;
    int half2 = (lane >> 3) & 1;
    auto compute = [&](int buf) {
        uint32_t sAh = sbase + buf * ZBUF;
        uint32_t sAl = sAh + ZTA;
        uint32_t sBh = sAh + 2 * ZTA;

        uint32_t ah[4][4], al[4][4];
#pragma unroll
        for (int mt = 0; mt < 4; mt++) {
            int row = warp_m * 64 + mt * 16 + lr + (sel & 1) * 8;
            int cc = sel >> 1;
            ldsm4(sAh + sw32(row, cc), ah[mt][0], ah[mt][1], ah[mt][2], ah[mt][3]);
            ldsm4(sAl + sw32(row, cc), al[mt][0], al[mt][1], al[mt][2], al[mt][3]);
        }
        uint32_t bh[6];
        {
            int row = warp_n * 24 + lr + (sel >> 1) * 8;
            int cc = sel & 1;
            ldsm4(sBh + sw32(row, cc), bh[0], bh[1], bh[2], bh[3]);
        }
        {
            int row = warp_n * 24 + 16 + lr;
            int cc = half2;
            ldsm2(sBh + sw32(row, cc), bh[4], bh[5]);
        }
#pragma unroll
        for (int mt = 0; mt < 4; mt++)
#pragma unroll
            for (int nt = 0; nt < 3; nt++) {
                mma16816h(acc[mt][nt][0], acc[mt][nt][1], acc[mt][nt][2], acc[mt][nt][3],
                          ah[mt][0], ah[mt][1], ah[mt][2], ah[mt][3], bh[nt * 2], bh[nt * 2 + 1]);
                mma16816h(acc[mt][nt][0], acc[mt][nt][1], acc[mt][nt][2], acc[mt][nt][3],
                          al[mt][0], al[mt][1], al[mt][2], al[mt][3], bh[nt * 2], bh[nt * 2 + 1]);
            }
    };

    stage(0, 0); cp_commit();
    stage(1, 1); cp_commit();
    for (int it = 0; it < NIT; it++) {
        if (it + 2 < NIT) {
            stage((it + 2) & 3, it + 2);
            cp_commit();
            cp_wait<2>();
        } else if (it + 1 < NIT) {
            cp_wait<1>();
        } else {
            cp_wait<0>();
        }
        __syncthreads();
        compute(it & 3);
    }

    float* __restrict__ Zb = g_Z + (size_t)b * LQ * KC;
    int r0l = lane >> 2;
    int c0l = (lane & 3) * 2;
#pragma unroll
    for (int mt = 0; mt < 4; mt++)
#pragma unroll
        for (int nt = 0; nt < 3; nt++) {
            int row = p0 + warp_m * 64 + mt * 16 + r0l;
            int col = n0 + warp_n * 24 + nt * 8 + c0l;
            *(float2*)(Zb + (size_t)row * KC + col) =
                make_float2(acc[mt][nt][0], acc[mt][nt][1]);
            *(float2*)(Zb + (size_t)(row + 8) * KC + col) =
                make_float2(acc[mt][nt][2], acc[mt][nt][3]);
        }
}

// ===================================================================
// Kernel 6: overlap-add (transposed conv gather), float4 per thread
// ===================================================================
__global__ void recon_kernel(float* __restrict__ out)
{
    int idx = blockIdx.x * blockDim.x + threadIdx.x;
    if (idx >= (int)(YSZ / 4)) return;
    int c4 = (idx & 15) * 4;
    int tmp = idx >> 4;
    int J = tmp & 127; tmp >>= 7;
    int I = tmp & 127;
    int b = tmp >> 7;

    int ri[2], rdh[2], rn = 0;
    if (I & 1) { ri[0] = (I - 1) >> 1; rdh[0] = 1; rn = 1; }
    else {
        ri[rn] = I >> 1; rdh[rn] = 0; rn++;
        if (I >= 2) { ri[rn] = (I >> 1) - 1; rdh[rn] = 2; rn++; }
    }
    int cj[2], cdw[2], cn = 0;
    if (J & 1) { cj[0] = (J - 1) >> 1; cdw[0] = 1; cn = 1; }
    else {
        cj[cn] = J >> 1; cdw[cn] = 0; cn++;
        if (J >= 2) { cj[cn] = (J >> 1) - 1; cdw[cn] = 2; cn++; }
    }

    const float* __restrict__ Zb = g_Z + (size_t)b * LQ * KC;
    float4 acc = make_float4(0.f, 0.f, 0.f, 0.f);
    for (int a = 0; a < rn; a++) {
        for (int bb = 0; bb < cn; bb++) {
            int l = ri[a] * 64 + cj[bb];
            int n = (rdh[a] * 3 + cdw[bb]) * 64 + c4;
            float4 v = *(const float4*)(Zb + (size_t)l * KC + n);
            acc.x += v.x; acc.y += v.y; acc.z += v.z; acc.w += v.w;
        }
    }
    acc.x *= 0.25f; acc.y *= 0.25f; acc.z *= 0.25f; acc.w *= 0.25f;
    size_t o = (((size_t)b * HFULL + I) * WFULL + J) * CCH + c4;
    *(float4*)(out + o) = acc;
}

// ===================================================================
extern "C" void kernel_launch(void* const* d_in, const int* in_sizes, int n_in,
                              void* d_out, int out_size)
{
    const float* x    = (const float*)d_in[0];
    const float* mask = (const float*)d_in[1];
    float* out = (float*)d_out;
    (void)in_sizes; (void)n_in; (void)out_size;

    // forked-capture side stream + events (created per call; no device memory)
    cudaStream_t s2;
    cudaStreamCreateWithFlags(&s2, cudaStreamNonBlocking);
    cudaEvent_t e1, e2;
    cudaEventCreateWithFlags(&e1, cudaEventDisableTiming);
    cudaEventCreateWithFlags(&e2, cudaEventDisableTiming);

    build_f_kernel<<<dim3(LQ / 4, BATCH), 256>>>(x);

    // fork: gemm_g + diag1 on s2 (depend only on g_Fhf)
    cudaEventRecord(e1, 0);
    cudaStreamWaitEvent(s2, e1, 0);
    gemm_g_kernel<<<dim3(32, 32, BATCH), 512, 0, s2>>>();
    diag1_kernel<<<dim3(LQ, BATCH), 256, 0, s2>>>();
    cudaEventRecord(e2, s2);

    // main branch: mask/invden/compaction/V path
    mm_invden_kernel<<<(BATCH * LQ + 255) / 256, 256>>>(mask);
    compact_kernel<<<BATCH, 1024>>>();
    vcompT_kernel<<<dim3(KC, BATCH), 256>>>(x);

    // join: diag2 needs diag1 (s2) + invden (main)
    cudaStreamWaitEvent(0, e2, 0);
    diag2_kernel<<<dim3(LQ, BATCH), 256>>>(out);
    fuse_softmax_kernel<<<dim3(512, BATCH), 256>>>(out);
    gemm_z_mma_kernel<<<dim3(6, 32, BATCH), 256>>>();
    recon_kernel<<<(int)(YSZ / 4 + 255) / 256, 256>>>(out);
}